// round 4
// baseline (speedup 1.0000x reference)
#include <cuda_runtime.h>
#include <cuda_bf16.h>
#include <cstdint>

#define DIM   768
#define INNER 96
#define NTOK  8
#define HW    1024
#define NB    64
#define EPS_LN 1e-5f

typedef unsigned long long ull;

// ---------------- scratch (device globals; no allocation allowed) ------------
__device__ __nv_bfloat16 g_Wt[INNER * DIM];        // W1*gamma, bf16, [i][c]
__device__ float g_colsum[INNER];
__device__ float g_bw1[INNER];
__device__ __align__(16) float g_U[NB * DIM * NTOK];   // sum_q x*r*e
__device__ __align__(16) float g_Z[NB * NTOK];         // sum_q e
__device__ __align__(16) float g_T[NB * NTOK];         // sum_q mu*r*e

// ---------------- helpers ----------------------------------------------------
__device__ __forceinline__ void mma_bf16(float* d,
    uint32_t a0, uint32_t a1, uint32_t a2, uint32_t a3,
    uint32_t b0, uint32_t b1)
{
    asm volatile(
        "mma.sync.aligned.m16n8k16.row.col.f32.bf16.bf16.f32 "
        "{%0,%1,%2,%3}, {%4,%5,%6,%7}, {%8,%9}, {%0,%1,%2,%3};"
        : "+f"(d[0]), "+f"(d[1]), "+f"(d[2]), "+f"(d[3])
        : "r"(a0), "r"(a1), "r"(a2), "r"(a3), "r"(b0), "r"(b1));
}

__device__ __forceinline__ void ldsm_x4(uint32_t* r, uint32_t addr) {
    asm volatile("ldmatrix.sync.aligned.m8n8.x4.shared.b16 {%0,%1,%2,%3}, [%4];"
        : "=r"(r[0]), "=r"(r[1]), "=r"(r[2]), "=r"(r[3]) : "r"(addr));
}
__device__ __forceinline__ void ldsm_x2(uint32_t* r, uint32_t addr) {
    asm volatile("ldmatrix.sync.aligned.m8n8.x2.shared.b16 {%0,%1}, [%2];"
        : "=r"(r[0]), "=r"(r[1]) : "r"(addr));
}

__device__ __forceinline__ void fma2(ull& d, ull a, ull b) {
    asm volatile("fma.rn.f32x2 %0, %1, %2, %0;" : "+l"(d) : "l"(a), "l"(b));
}

// ---------------- setup: fold gamma into W1, precompute column sums ----------
__global__ void setup_kernel(const float* __restrict__ w1,
                             const float* __restrict__ gamma,
                             const float* __restrict__ beta,
                             const float* __restrict__ b1)
{
    int i = blockIdx.x;
    int t = threadIdx.x;
    float a = 0.f, bs = 0.f;
    for (int c = t; c < DIM; c += 256) {
        float w  = w1[c * INNER + i];
        float gw = gamma[c] * w;
        g_Wt[i * DIM + c] = __float2bfloat16(gw);
        a  += gw;
        bs += beta[c] * w;
    }
    __shared__ float ra[256], rb[256];
    ra[t] = a; rb[t] = bs;
    __syncthreads();
    for (int s = 128; s > 0; s >>= 1) {
        if (t < s) { ra[t] += ra[t + s]; rb[t] += rb[t + s]; }
        __syncthreads();
    }
    if (t == 0) { g_colsum[i] = ra[0]; g_bw1[i] = rb[0] + b1[i]; }
}

// ---------------- zero accumulators ------------------------------------------
__global__ void zero_kernel()
{
    int idx = blockIdx.x * 256 + threadIdx.x;
    float4 z = make_float4(0.f, 0.f, 0.f, 0.f);
    ((float4*)g_U)[idx] = z;
    if (blockIdx.x == 0) {
        if (threadIdx.x < 128)       ((float4*)g_Z)[threadIdx.x]       = z;
        else                         ((float4*)g_T)[threadIdx.x - 128] = z;
    }
}

// ---------------- fused kernel A ----------------------------------------------
// Per block: (b, q-tile of 128). Mainloop bf16 MMA -> logits; exp; tile-local
// U-GEMM re-reading the (L2-hot) x tile; atomic partials to g_U/g_Z/g_T.
constexpr int XP  = 40;    // bf16 pitch of mainloop X tile
constexpr int WP  = 40;
constexpr int XSP = 132;   // float pitch of phase-4 staged x rows (conflict-free)

__global__ __launch_bounds__(256, 2) void fusedA_kernel(
    const float* __restrict__ x, const float* __restrict__ w2)
{
    // union region: mainloop Xs(20480B)+Ws(15360B) = 35840B
    //               reused later: logitsS (4096B), phase-4 xs (2*16896B)
    __shared__ __align__(16) char uBuf[35840];
    __shared__ float sumS[128], sqS[128], muS[128], rS[128];
    __shared__ float w2S[INNER * NTOK];
    __shared__ float colsumS[INNER], bw1S[INNER];
    __shared__ __align__(16) ull ew2S[NTOK * 66];   // w pairs, padded pitch

    __nv_bfloat16* Xs = (__nv_bfloat16*)uBuf;            // [2][128*XP]
    __nv_bfloat16* Ws = (__nv_bfloat16*)(uBuf + 20480);  // [2][INNER*WP]
    float* logitsS = (float*)uBuf;                       // after mainloop
    float* xsBuf   = (float*)uBuf;                       // phase 4: [2][32*XSP]

    int t   = threadIdx.x;
    int blk = blockIdx.x;
    int b   = blk >> 3;
    int q0  = (blk & 7) << 7;

    if (t < 128) { sumS[t] = 0.f; sqS[t] = 0.f; }
    for (int i = t; i < INNER * NTOK; i += 256) w2S[i] = w2[i];
    if (t < INNER) { colsumS[t] = g_colsum[t]; bw1S[t] = g_bw1[t]; }

    int qi = t & 63;        // token pair: rows 2qi, 2qi+1
    int ci = t >> 6;        // channel slice 0..3
    const float* xb = x + ((size_t)b * DIM) * HW + q0 + qi * 2;

    float s1a = 0.f, s1b = 0.f, s2a = 0.f, s2b = 0.f;
    float acc[2][6][4];
#pragma unroll
    for (int mt = 0; mt < 2; mt++)
#pragma unroll
        for (int nt = 0; nt < 6; nt++)
#pragma unroll
            for (int r = 0; r < 4; r++) acc[mt][nt][r] = 0.f;

    int w    = t >> 5, lane = t & 31;
    int wm   = w & 3,  wn   = w >> 2;
    int gid  = lane >> 2, tid = lane & 3;
    int wi   = t >> 1, whf = t & 1;

    uint32_t aAddr0 = (uint32_t)__cvta_generic_to_shared(
        &Xs[(wm * 32 + (lane & 15)) * XP + (lane >> 4) * 8]);
    uint32_t aAddr1 = aAddr0 + 16 * XP * 2;
    uint32_t bAddr  = (uint32_t)__cvta_generic_to_shared(
        &Ws[(wn * 48 + (lane & 7)) * WP + ((lane >> 3) & 1) * 8]);
    const uint32_t XBUF = 128 * XP * 2;
    const uint32_t WBUF = INNER * WP * 2;

    float2 xv[8];
    uint4 wv0, wv1;
#pragma unroll
    for (int j = 0; j < 8; j++)
        xv[j] = *(const float2*)(xb + (size_t)(ci * 8 + j) * HW);
    if (t < 192) {
        const uint4* src = (const uint4*)(g_Wt + wi * DIM + whf * 16);
        wv0 = src[0]; wv1 = src[1];
    }

    for (int kc = 0; kc < 24; kc++) {
        int buf = kc & 1;
#pragma unroll
        for (int j = 0; j < 8; j++) {
            s1a += xv[j].x; s2a += xv[j].x * xv[j].x;
            s1b += xv[j].y; s2b += xv[j].y * xv[j].y;
        }
        __nv_bfloat162 p0[4], p1[4];
#pragma unroll
        for (int j = 0; j < 4; j++) {
            p0[j] = __floats2bfloat162_rn(xv[2*j].x, xv[2*j+1].x);
            p1[j] = __floats2bfloat162_rn(xv[2*j].y, xv[2*j+1].y);
        }
        *(uint4*)&Xs[buf * (128*XP) + (qi * 2)     * XP + ci * 8] = *(uint4*)p0;
        *(uint4*)&Xs[buf * (128*XP) + (qi * 2 + 1) * XP + ci * 8] = *(uint4*)p1;
        if (t < 192) {
            uint4* dst = (uint4*)&Ws[buf * (INNER*WP) + wi * WP + whf * 16];
            dst[0] = wv0; dst[1] = wv1;
        }
        __syncthreads();

        if (kc < 23) {
            int c0 = (kc + 1) * 32;
#pragma unroll
            for (int j = 0; j < 8; j++)
                xv[j] = *(const float2*)(xb + (size_t)(c0 + ci * 8 + j) * HW);
            if (t < 192) {
                const uint4* src = (const uint4*)(g_Wt + wi * DIM + c0 + whf * 16);
                wv0 = src[0]; wv1 = src[1];
            }
        }

        uint32_t xo = buf * XBUF, wo = buf * WBUF;
#pragma unroll
        for (int ks = 0; ks < 2; ks++) {
            uint32_t af0[4], af1[4];
            ldsm_x4(af0, aAddr0 + xo + ks * 32);
            ldsm_x4(af1, aAddr1 + xo + ks * 32);
            uint32_t bfrag[6][2];
#pragma unroll
            for (int nt = 0; nt < 6; nt++)
                ldsm_x2(bfrag[nt], bAddr + wo + nt * 8 * WP * 2 + ks * 32);
#pragma unroll
            for (int nt = 0; nt < 6; nt++) {
                mma_bf16(acc[0][nt], af0[0], af0[1], af0[2], af0[3],
                         bfrag[nt][0], bfrag[nt][1]);
                mma_bf16(acc[1][nt], af1[0], af1[1], af1[2], af1[3],
                         bfrag[nt][0], bfrag[nt][1]);
            }
        }
    }

    // ---- token stats ----
    atomicAdd(&sumS[qi * 2],     s1a); atomicAdd(&sqS[qi * 2],     s2a);
    atomicAdd(&sumS[qi * 2 + 1], s1b); atomicAdd(&sqS[qi * 2 + 1], s2b);
    __syncthreads();                    // mainloop smem reads done; safe to overlay
    if (t < 128) {
        float mu  = sumS[t] * (1.f / DIM);
        float var = sqS[t] * (1.f / DIM) - mu * mu;
        float r   = rsqrtf(var + EPS_LN);
        muS[t] = mu; rS[t] = r;
    }
    ((float4*)logitsS)[t] = make_float4(0.f, 0.f, 0.f, 0.f);  // zero 1024 floats
    __syncthreads();

    // ---- epilogue: y -> gelu -> logits ----
#pragma unroll
    for (int mt = 0; mt < 2; mt++) {
#pragma unroll
        for (int hf = 0; hf < 2; hf++) {
            int ql   = wm * 32 + mt * 16 + hf * 8 + gid;
            float mu = muS[ql], r = rS[ql];
            float pl[NTOK];
#pragma unroll
            for (int n = 0; n < NTOK; n++) pl[n] = 0.f;
#pragma unroll
            for (int nt = 0; nt < 6; nt++) {
#pragma unroll
                for (int ch = 0; ch < 2; ch++) {
                    int i   = wn * 48 + nt * 8 + tid * 2 + ch;
                    float v = acc[mt][nt][hf * 2 + ch];
                    float y = r * (v - mu * colsumS[i]) + bw1S[i];
                    float h = 0.5f * y * (1.f + erff(y * 0.70710678f));
#pragma unroll
                    for (int n = 0; n < NTOK; n++) pl[n] += h * w2S[i * NTOK + n];
                }
            }
#pragma unroll
            for (int n = 0; n < NTOK; n++) {
                pl[n] += __shfl_xor_sync(0xffffffffu, pl[n], 1);
                pl[n] += __shfl_xor_sync(0xffffffffu, pl[n], 2);
            }
            if (tid == 0) {
#pragma unroll
                for (int n = 0; n < NTOK; n++)
                    atomicAdd(&logitsS[ql * NTOK + n], pl[n]);
            }
        }
    }
    __syncthreads();

    // ---- phase 3: e = exp(logit) (unnormalized, logits are small);
    //      w = r*e pairs into ew2S; partial Z, T -> global atomics ----
    {
        float zp[2], tp[2]; int ns[2];
#pragma unroll
        for (int it = 0; it < 2; it++) {
            int i = t + it * 256;
            int n = i >> 6, p = i & 63;
            ns[it] = n;
            float l0 = logitsS[(2*p)     * NTOK + n];
            float l1 = logitsS[(2*p + 1) * NTOK + n];
            float e0 = expf(l0), e1 = expf(l1);
            float w0 = rS[2*p] * e0, w1 = rS[2*p+1] * e1;
            float2 wpk = make_float2(w0, w1);
            ew2S[n * 66 + p] = *(ull*)&wpk;
            zp[it] = e0 + e1;
            tp[it] = muS[2*p] * w0 + muS[2*p+1] * w1;
        }
#pragma unroll
        for (int o = 16; o; o >>= 1) {
            zp[0] += __shfl_xor_sync(0xffffffffu, zp[0], o);
            zp[1] += __shfl_xor_sync(0xffffffffu, zp[1], o);
            tp[0] += __shfl_xor_sync(0xffffffffu, tp[0], o);
            tp[1] += __shfl_xor_sync(0xffffffffu, tp[1], o);
        }
        if (lane == 0) {
            atomicAdd(&g_Z[b * NTOK + ns[0]], zp[0]);
            atomicAdd(&g_Z[b * NTOK + ns[1]], zp[1]);
            atomicAdd(&g_T[b * NTOK + ns[0]], tp[0]);
            atomicAdd(&g_T[b * NTOK + ns[1]], tp[1]);
        }
    }
    __syncthreads();

    // ---- phase 4: U[c,n] += sum_q x[c,q] * w[q,n] over this tile.
    //      x re-read (L2-hot) coalesced -> smem staging (double buffered);
    //      lane = (c4, n): no cross-lane reduction, 1 atomic per lane/group ----
    {
        int c4 = lane >> 3;            // 0..3
        int nn = lane & 7;             // 0..7
        int cg = w * 4 + c4;           // channel within 32-group
        const float* xg = x + ((size_t)b * DIM) * HW + q0;

        float4 pf[4];
#pragma unroll
        for (int k = 0; k < 4; k++) {
            int idx = k * 256 + t;
            int ch = idx >> 5, q4 = idx & 31;
            pf[k] = *(const float4*)(xg + (size_t)ch * HW + q4 * 4);
        }
#pragma unroll
        for (int k = 0; k < 4; k++) {
            int idx = k * 256 + t;
            int ch = idx >> 5, q4 = idx & 31;
            *(float4*)&xsBuf[ch * XSP + q4 * 4] = pf[k];
        }
        __syncthreads();

        for (int g = 0; g < 24; g++) {
            int buf = g & 1;
            if (g < 23) {
#pragma unroll
                for (int k = 0; k < 4; k++) {
                    int idx = k * 256 + t;
                    int ch = idx >> 5, q4 = idx & 31;
                    pf[k] = *(const float4*)(xg + (size_t)((g + 1) * 32 + ch) * HW + q4 * 4);
                }
            }
            ull uacc = 0ull;
            const float* xrow = &xsBuf[buf * (32 * XSP) + cg * XSP];
            const ull*  wrow  = &ew2S[nn * 66];
#pragma unroll 8
            for (int qc = 0; qc < 32; qc++) {
                ulonglong2 xp = *(const ulonglong2*)(xrow + qc * 4);
                ulonglong2 wp = *(const ulonglong2*)(wrow + qc * 2);
                fma2(uacc, xp.x, wp.x);
                fma2(uacc, xp.y, wp.y);
            }
            float lo = __int_as_float((unsigned)(uacc & 0xffffffffull));
            float hi = __int_as_float((unsigned)(uacc >> 32));
            atomicAdd(&g_U[(((size_t)b * DIM) + g * 32 + cg) * NTOK + nn], lo + hi);

            if (g < 23) {
                int nb = (g + 1) & 1;
#pragma unroll
                for (int k = 0; k < 4; k++) {
                    int idx = k * 256 + t;
                    int ch = idx >> 5, q4 = idx & 31;
                    *(float4*)&xsBuf[nb * (32 * XSP) + ch * XSP + q4 * 4] = pf[k];
                }
            }
            __syncthreads();
        }
    }
}

// ---------------- finalize: out = (gamma*(U-T)/Z + beta)/1024 -----------------
__global__ void finalize_kernel(const float* __restrict__ gamma,
                                const float* __restrict__ beta,
                                float* __restrict__ out)
{
    int b = blockIdx.x;
    int c = threadIdx.x;   // 768
    __shared__ float invZ[NTOK], Tt[NTOK];
    if (c < NTOK) {
        invZ[c] = 1.f / g_Z[b * NTOK + c];
        Tt[c]   = g_T[b * NTOK + c];
    }
    __syncthreads();
    float g  = gamma[c] * (1.f / 1024.f);
    float be = beta[c]  * (1.f / 1024.f);
    const float4* Up = (const float4*)&g_U[(((size_t)b * DIM) + c) * NTOK];
    float4 u0 = Up[0], u1 = Up[1];
    float4 o0, o1;
    o0.x = g * (u0.x - Tt[0]) * invZ[0] + be;
    o0.y = g * (u0.y - Tt[1]) * invZ[1] + be;
    o0.z = g * (u0.z - Tt[2]) * invZ[2] + be;
    o0.w = g * (u0.w - Tt[3]) * invZ[3] + be;
    o1.x = g * (u1.x - Tt[4]) * invZ[4] + be;
    o1.y = g * (u1.y - Tt[5]) * invZ[5] + be;
    o1.z = g * (u1.z - Tt[6]) * invZ[6] + be;
    o1.w = g * (u1.w - Tt[7]) * invZ[7] + be;
    float4* Op = (float4*)&out[(((size_t)b * DIM) + c) * NTOK];
    Op[0] = o0; Op[1] = o1;
}

// ---------------- launcher ----------------------------------------------------
extern "C" void kernel_launch(void* const* d_in, const int* in_sizes, int n_in,
                              void* d_out, int out_size)
{
    const float* x     = (const float*)d_in[0];
    const float* gamma = (const float*)d_in[1];
    const float* beta  = (const float*)d_in[2];
    const float* w1    = (const float*)d_in[3];
    const float* b1    = (const float*)d_in[4];
    const float* w2    = (const float*)d_in[5];
    // d_in[6] = b2: constant shift before token softmax -> cancels exactly.
    float* out = (float*)d_out;

    setup_kernel<<<INNER, 256>>>(w1, gamma, beta, b1);
    zero_kernel<<<384, 256>>>();
    fusedA_kernel<<<NB * 8, 256>>>(x, w2);
    finalize_kernel<<<NB, 768>>>(gamma, beta, out);
}

// round 5
// speedup vs baseline: 1.1469x; 1.1469x over previous
#include <cuda_runtime.h>
#include <cuda_bf16.h>
#include <cstdint>

#define DIM   768
#define INNER 96
#define NTOK  8
#define HW    1024
#define NB    64
#define EPS_LN 1e-5f

typedef unsigned long long ull;

// ---------------- scratch (device globals; no allocation allowed) ------------
__device__ __nv_bfloat16 g_Wt[INNER * DIM];        // W1*gamma, bf16, [i][c]
__device__ float g_colsum[INNER];
__device__ float g_bw1[INNER];
__device__ float g_r[NB * HW];
__device__ float g_mu[NB * HW];
__device__ float g_logitsT[NB * NTOK * HW];
__device__ float g_attnwT[NB * NTOK * HW];         // r_p * attn[p,n], [b][n][p]
__device__ float g_S[NB * NTOK];

// ---------------- helpers ----------------------------------------------------
__device__ __forceinline__ void mma_bf16(float* d,
    uint32_t a0, uint32_t a1, uint32_t a2, uint32_t a3,
    uint32_t b0, uint32_t b1)
{
    asm volatile(
        "mma.sync.aligned.m16n8k16.row.col.f32.bf16.bf16.f32 "
        "{%0,%1,%2,%3}, {%4,%5,%6,%7}, {%8,%9}, {%0,%1,%2,%3};"
        : "+f"(d[0]), "+f"(d[1]), "+f"(d[2]), "+f"(d[3])
        : "r"(a0), "r"(a1), "r"(a2), "r"(a3), "r"(b0), "r"(b1));
}

__device__ __forceinline__ void ldsm_x4(uint32_t* r, uint32_t addr) {
    asm volatile("ldmatrix.sync.aligned.m8n8.x4.shared.b16 {%0,%1,%2,%3}, [%4];"
        : "=r"(r[0]), "=r"(r[1]), "=r"(r[2]), "=r"(r[3]) : "r"(addr));
}
__device__ __forceinline__ void ldsm_x2(uint32_t* r, uint32_t addr) {
    asm volatile("ldmatrix.sync.aligned.m8n8.x2.shared.b16 {%0,%1}, [%2];"
        : "=r"(r[0]), "=r"(r[1]) : "r"(addr));
}

__device__ __forceinline__ void fma2(ull& d, ull a, ull b) {
    asm volatile("fma.rn.f32x2 %0, %1, %2, %0;" : "+l"(d) : "l"(a), "l"(b));
}

// ---------------- setup: fold gamma into W1, precompute column sums ----------
__global__ void setup_kernel(const float* __restrict__ w1,
                             const float* __restrict__ gamma,
                             const float* __restrict__ beta,
                             const float* __restrict__ b1)
{
    int i = blockIdx.x;
    int t = threadIdx.x;
    float a = 0.f, bs = 0.f;
    for (int c = t; c < DIM; c += 256) {
        float w  = w1[c * INNER + i];
        float gw = gamma[c] * w;
        g_Wt[i * DIM + c] = __float2bfloat16(gw);
        a  += gw;
        bs += beta[c] * w;
    }
    __shared__ float ra[256], rb[256];
    ra[t] = a; rb[t] = bs;
    __syncthreads();
    for (int s = 128; s > 0; s >>= 1) {
        if (t < s) { ra[t] += ra[t + s]; rb[t] += rb[t + s]; }
        __syncthreads();
    }
    if (t == 0) { g_colsum[i] = ra[0]; g_bw1[i] = rb[0] + b1[i]; }
}

// ---------------- pass A: LN stats + MLP logits, pipelined bf16 mma ----------
constexpr int XP = 40;
constexpr int WP = 40;

__global__ __launch_bounds__(256, 2) void passA_kernel(
    const float* __restrict__ x, const float* __restrict__ w2)
{
    __shared__ __nv_bfloat16 Xs[2][128 * XP];
    __shared__ __nv_bfloat16 Ws[2][INNER * WP];
    __shared__ float logitsS[128 * NTOK];
    __shared__ float sumS[128], sqS[128], muS[128], rS[128];
    __shared__ float w2S[INNER * NTOK];
    __shared__ float colsumS[INNER], bw1S[INNER];

    int t   = threadIdx.x;
    int blk = blockIdx.x;
    int b   = blk >> 3;
    int q0  = (blk & 7) << 7;

    for (int i = t; i < 128 * NTOK; i += 256) logitsS[i] = 0.f;
    if (t < 128) { sumS[t] = 0.f; sqS[t] = 0.f; }
    for (int i = t; i < INNER * NTOK; i += 256) w2S[i] = w2[i];
    if (t < INNER) { colsumS[t] = g_colsum[t]; bw1S[t] = g_bw1[t]; }

    int qi = t & 63;
    int ci = t >> 6;
    const float* xb = x + ((size_t)b * DIM) * HW + q0 + qi * 2;

    float s1a = 0.f, s1b = 0.f, s2a = 0.f, s2b = 0.f;
    float acc[2][6][4];
#pragma unroll
    for (int mt = 0; mt < 2; mt++)
#pragma unroll
        for (int nt = 0; nt < 6; nt++)
#pragma unroll
            for (int r = 0; r < 4; r++) acc[mt][nt][r] = 0.f;

    int w    = t >> 5, lane = t & 31;
    int wm   = w & 3,  wn   = w >> 2;
    int gid  = lane >> 2, tid = lane & 3;
    int wi   = t >> 1, whf = t & 1;

    uint32_t aAddr0 = (uint32_t)__cvta_generic_to_shared(
        &Xs[0][(wm * 32 + (lane & 15)) * XP + (lane >> 4) * 8]);
    uint32_t aAddr1 = aAddr0 + 16 * XP * 2;
    uint32_t bAddr  = (uint32_t)__cvta_generic_to_shared(
        &Ws[0][(wn * 48 + (lane & 7)) * WP + ((lane >> 3) & 1) * 8]);
    const uint32_t XBUF = 128 * XP * 2;
    const uint32_t WBUF = INNER * WP * 2;

    float2 xv[8];
    uint4 wv0, wv1;
#pragma unroll
    for (int j = 0; j < 8; j++)
        xv[j] = *(const float2*)(xb + (size_t)(ci * 8 + j) * HW);
    if (t < 192) {
        const uint4* src = (const uint4*)(g_Wt + wi * DIM + whf * 16);
        wv0 = src[0]; wv1 = src[1];
    }

    for (int kc = 0; kc < 24; kc++) {
        int buf = kc & 1;
#pragma unroll
        for (int j = 0; j < 8; j++) {
            s1a += xv[j].x; s2a += xv[j].x * xv[j].x;
            s1b += xv[j].y; s2b += xv[j].y * xv[j].y;
        }
        __nv_bfloat162 p0[4], p1[4];
#pragma unroll
        for (int j = 0; j < 4; j++) {
            p0[j] = __floats2bfloat162_rn(xv[2*j].x, xv[2*j+1].x);
            p1[j] = __floats2bfloat162_rn(xv[2*j].y, xv[2*j+1].y);
        }
        *(uint4*)&Xs[buf][(qi * 2)     * XP + ci * 8] = *(uint4*)p0;
        *(uint4*)&Xs[buf][(qi * 2 + 1) * XP + ci * 8] = *(uint4*)p1;
        if (t < 192) {
            uint4* dst = (uint4*)&Ws[buf][wi * WP + whf * 16];
            dst[0] = wv0; dst[1] = wv1;
        }
        __syncthreads();

        if (kc < 23) {
            int c0 = (kc + 1) * 32;
#pragma unroll
            for (int j = 0; j < 8; j++)
                xv[j] = *(const float2*)(xb + (size_t)(c0 + ci * 8 + j) * HW);
            if (t < 192) {
                const uint4* src = (const uint4*)(g_Wt + wi * DIM + c0 + whf * 16);
                wv0 = src[0]; wv1 = src[1];
            }
        }

        uint32_t xo = buf * XBUF, wo = buf * WBUF;
#pragma unroll
        for (int ks = 0; ks < 2; ks++) {
            uint32_t af0[4], af1[4];
            ldsm_x4(af0, aAddr0 + xo + ks * 32);
            ldsm_x4(af1, aAddr1 + xo + ks * 32);
            uint32_t bfrag[6][2];
#pragma unroll
            for (int nt = 0; nt < 6; nt++)
                ldsm_x2(bfrag[nt], bAddr + wo + nt * 8 * WP * 2 + ks * 32);
#pragma unroll
            for (int nt = 0; nt < 6; nt++) {
                mma_bf16(acc[0][nt], af0[0], af0[1], af0[2], af0[3],
                         bfrag[nt][0], bfrag[nt][1]);
                mma_bf16(acc[1][nt], af1[0], af1[1], af1[2], af1[3],
                         bfrag[nt][0], bfrag[nt][1]);
            }
        }
    }

    // token stats
    atomicAdd(&sumS[qi * 2],     s1a); atomicAdd(&sqS[qi * 2],     s2a);
    atomicAdd(&sumS[qi * 2 + 1], s1b); atomicAdd(&sqS[qi * 2 + 1], s2b);
    __syncthreads();
    if (t < 128) {
        float mu  = sumS[t] * (1.f / DIM);
        float var = sqS[t] * (1.f / DIM) - mu * mu;
        float r   = rsqrtf(var + EPS_LN);
        muS[t] = mu; rS[t] = r;
        g_mu[b * HW + q0 + t] = mu;
        g_r [b * HW + q0 + t] = r;
    }
    __syncthreads();

    // epilogue: y -> gelu -> logits
#pragma unroll
    for (int mt = 0; mt < 2; mt++) {
#pragma unroll
        for (int hf = 0; hf < 2; hf++) {
            int ql   = wm * 32 + mt * 16 + hf * 8 + gid;
            float mu = muS[ql], r = rS[ql];
            float pl[NTOK];
#pragma unroll
            for (int n = 0; n < NTOK; n++) pl[n] = 0.f;
#pragma unroll
            for (int nt = 0; nt < 6; nt++) {
#pragma unroll
                for (int ch = 0; ch < 2; ch++) {
                    int i   = wn * 48 + nt * 8 + tid * 2 + ch;
                    float v = acc[mt][nt][hf * 2 + ch];
                    float y = r * (v - mu * colsumS[i]) + bw1S[i];
                    float h = 0.5f * y * (1.f + erff(y * 0.70710678f));
#pragma unroll
                    for (int n = 0; n < NTOK; n++) pl[n] += h * w2S[i * NTOK + n];
                }
            }
#pragma unroll
            for (int n = 0; n < NTOK; n++) {
                pl[n] += __shfl_xor_sync(0xffffffffu, pl[n], 1);
                pl[n] += __shfl_xor_sync(0xffffffffu, pl[n], 2);
            }
            if (tid == 0) {
#pragma unroll
                for (int n = 0; n < NTOK; n++)
                    atomicAdd(&logitsS[ql * NTOK + n], pl[n]);
            }
        }
    }
    __syncthreads();
    for (int idx = t; idx < 128 * NTOK; idx += 256) {
        int n = idx >> 7, q = idx & 127;
        g_logitsT[((size_t)b * NTOK + n) * HW + q0 + q] = logitsS[q * NTOK + n];
    }
}

// ---------------- pass B: softmax over tokens, per (b, n) --------------------
__global__ void passB_kernel()
{
    int b = blockIdx.x;
    int w = threadIdx.x >> 5, lane = threadIdx.x & 31;
    const float* lp  = g_logitsT + ((size_t)b * NTOK + w) * HW;
    const float* mup = g_mu + (size_t)b * HW;
    const float* rp  = g_r  + (size_t)b * HW;

    float m = -1e30f;
    for (int j = 0; j < 32; j++) m = fmaxf(m, lp[lane + j * 32]);
#pragma unroll
    for (int o = 16; o; o >>= 1) m = fmaxf(m, __shfl_xor_sync(0xffffffffu, m, o));

    float Z = 0.f, Sm = 0.f;
    for (int j = 0; j < 32; j++) {
        int p  = lane + j * 32;
        float e = expf(lp[p] - m);
        Z  += e;
        Sm += mup[p] * rp[p] * e;
    }
#pragma unroll
    for (int o = 16; o; o >>= 1) {
        Z  += __shfl_xor_sync(0xffffffffu, Z,  o);
        Sm += __shfl_xor_sync(0xffffffffu, Sm, o);
    }
    float invZ = 1.f / Z;
    float* ap = g_attnwT + ((size_t)b * NTOK + w) * HW;
    for (int j = 0; j < 32; j++) {
        int p  = lane + j * 32;
        float e = expf(lp[p] - m);
        ap[p] = rp[p] * e * invZ;
    }
    if (lane == 0) g_S[b * NTOK + w] = Sm * invZ;
}

// ---------------- pass C: 512 blocks x 96 channels, 2 ch/warp ----------------
__global__ __launch_bounds__(256, 3) void passC_kernel(
    const float* __restrict__ x, const float* __restrict__ gamma,
    const float* __restrict__ beta, float* __restrict__ out)
{
    __shared__ float awS[NTOK * HW];   // 32 KB, serves 96 channels of work
    __shared__ float Ss[NTOK];
    int t   = threadIdx.x;
    int blk = blockIdx.x;
    int b   = (NB - 1) - (blk >> 3);   // reversed: hit passA's L2 tail
    int ct  = blk & 7;                 // 96-channel slab

    for (int i = t * 4; i < NTOK * HW; i += 1024)
        *(float4*)&awS[i] = *(const float4*)&g_attnwT[(size_t)b * NTOK * HW + i];
    if (t < NTOK) Ss[t] = g_S[b * NTOK + t];
    __syncthreads();

    int w = t >> 5, lane = t & 31;
#pragma unroll 1
    for (int it = 0; it < 6; it++) {
        int c = ct * 96 + it * 16 + w * 2;      // warp handles 2 channels
        const float* xb = x + ((size_t)b * DIM + c) * HW;

        ull acc2[2][NTOK];
#pragma unroll
        for (int k = 0; k < 2; k++)
#pragma unroll
            for (int n = 0; n < NTOK; n++) acc2[k][n] = 0ull;

#pragma unroll
        for (int j = 0; j < 8; j++) {
            int q4 = lane * 4 + j * 128;
            ulonglong2 xp0 = *(const ulonglong2*)(xb + q4);
            ulonglong2 xp1 = *(const ulonglong2*)(xb + HW + q4);
#pragma unroll
            for (int n = 0; n < NTOK; n++) {
                ulonglong2 a = *(const ulonglong2*)(awS + n * HW + q4);
                fma2(acc2[0][n], xp0.x, a.x);
                fma2(acc2[0][n], xp0.y, a.y);
                fma2(acc2[1][n], xp1.x, a.x);
                fma2(acc2[1][n], xp1.y, a.y);
            }
        }
#pragma unroll
        for (int k = 0; k < 2; k++) {
#pragma unroll
            for (int n = 0; n < NTOK; n++) {
                float lo = __int_as_float((unsigned)(acc2[k][n] & 0xffffffffull));
                float hi = __int_as_float((unsigned)(acc2[k][n] >> 32));
                float v  = lo + hi;
#pragma unroll
                for (int o = 16; o; o >>= 1) v += __shfl_xor_sync(0xffffffffu, v, o);
                if (lane == 0) {
                    float g  = gamma[c + k], be = beta[c + k];
                    out[(((size_t)b * DIM) + (c + k)) * NTOK + n] =
                        (g * (v - Ss[n]) + be) * (1.f / 1024.f);
                }
            }
        }
    }
}

// ---------------- launcher ----------------------------------------------------
extern "C" void kernel_launch(void* const* d_in, const int* in_sizes, int n_in,
                              void* d_out, int out_size)
{
    const float* x     = (const float*)d_in[0];
    const float* gamma = (const float*)d_in[1];
    const float* beta  = (const float*)d_in[2];
    const float* w1    = (const float*)d_in[3];
    const float* b1    = (const float*)d_in[4];
    const float* w2    = (const float*)d_in[5];
    // d_in[6] = b2: constant shift before token softmax -> cancels exactly.
    float* out = (float*)d_out;

    setup_kernel<<<INNER, 256>>>(w1, gamma, beta, b1);
    passA_kernel<<<NB * 8, 256>>>(x, w2);
    passB_kernel<<<NB, 256>>>();
    passC_kernel<<<NB * 8, 256>>>(x, gamma, beta, out);
}

// round 6
// speedup vs baseline: 1.2362x; 1.0778x over previous
#include <cuda_runtime.h>
#include <cuda_bf16.h>
#include <cstdint>

#define DIM   768
#define INNER 96
#define NTOK  8
#define HW    1024
#define NB    64
#define EPS_LN 1e-5f

typedef unsigned long long ull;

// ---------------- scratch (device globals; no allocation allowed) ------------
__device__ __nv_bfloat16 g_Wt[INNER * DIM];        // W1*gamma, bf16, [i][c]
__device__ float g_colsum[INNER];
__device__ float g_bw1[INNER];
__device__ float g_r[NB * HW];
__device__ float g_mu[NB * HW];
__device__ float g_logitsT[NB * NTOK * HW];
__device__ float g_attnwT[NB * NTOK * HW];         // r_p * attn[p,n], [b][n][p]
__device__ float g_S[NB * NTOK];

// ---------------- helpers ----------------------------------------------------
__device__ __forceinline__ void mma_bf16(float* d,
    uint32_t a0, uint32_t a1, uint32_t a2, uint32_t a3,
    uint32_t b0, uint32_t b1)
{
    asm volatile(
        "mma.sync.aligned.m16n8k16.row.col.f32.bf16.bf16.f32 "
        "{%0,%1,%2,%3}, {%4,%5,%6,%7}, {%8,%9}, {%0,%1,%2,%3};"
        : "+f"(d[0]), "+f"(d[1]), "+f"(d[2]), "+f"(d[3])
        : "r"(a0), "r"(a1), "r"(a2), "r"(a3), "r"(b0), "r"(b1));
}

__device__ __forceinline__ void ldsm_x4(uint32_t* r, uint32_t addr) {
    asm volatile("ldmatrix.sync.aligned.m8n8.x4.shared.b16 {%0,%1,%2,%3}, [%4];"
        : "=r"(r[0]), "=r"(r[1]), "=r"(r[2]), "=r"(r[3]) : "r"(addr));
}
__device__ __forceinline__ void ldsm_x2(uint32_t* r, uint32_t addr) {
    asm volatile("ldmatrix.sync.aligned.m8n8.x2.shared.b16 {%0,%1}, [%2];"
        : "=r"(r[0]), "=r"(r[1]) : "r"(addr));
}

// ---------------- setup: fold gamma into W1, precompute column sums ----------
__global__ void setup_kernel(const float* __restrict__ w1,
                             const float* __restrict__ gamma,
                             const float* __restrict__ beta,
                             const float* __restrict__ b1)
{
    int i = blockIdx.x;
    int t = threadIdx.x;
    float a = 0.f, bs = 0.f;
    for (int c = t; c < DIM; c += 256) {
        float w  = w1[c * INNER + i];
        float gw = gamma[c] * w;
        g_Wt[i * DIM + c] = __float2bfloat16(gw);
        a  += gw;
        bs += beta[c] * w;
    }
    __shared__ float ra[256], rb[256];
    ra[t] = a; rb[t] = bs;
    __syncthreads();
    for (int s = 128; s > 0; s >>= 1) {
        if (t < s) { ra[t] += ra[t + s]; rb[t] += rb[t + s]; }
        __syncthreads();
    }
    if (t == 0) { g_colsum[i] = ra[0]; g_bw1[i] = rb[0] + b1[i]; }
}

// ---------------- pass A: LN stats + MLP logits, pipelined bf16 mma ----------
constexpr int XP = 40;
constexpr int WP = 40;

__global__ __launch_bounds__(256, 2) void passA_kernel(
    const float* __restrict__ x, const float* __restrict__ w2)
{
    __shared__ __nv_bfloat16 Xs[2][128 * XP];
    __shared__ __nv_bfloat16 Ws[2][INNER * WP];
    __shared__ float logitsS[128 * NTOK];
    __shared__ float sumS[128], sqS[128], muS[128], rS[128];
    __shared__ float w2S[INNER * NTOK];
    __shared__ float colsumS[INNER], bw1S[INNER];

    int t   = threadIdx.x;
    int blk = blockIdx.x;
    int b   = blk >> 3;
    int q0  = (blk & 7) << 7;

    for (int i = t; i < 128 * NTOK; i += 256) logitsS[i] = 0.f;
    if (t < 128) { sumS[t] = 0.f; sqS[t] = 0.f; }
    for (int i = t; i < INNER * NTOK; i += 256) w2S[i] = w2[i];
    if (t < INNER) { colsumS[t] = g_colsum[t]; bw1S[t] = g_bw1[t]; }

    int qi = t & 63;
    int ci = t >> 6;
    const float* xb = x + ((size_t)b * DIM) * HW + q0 + qi * 2;

    float s1a = 0.f, s1b = 0.f, s2a = 0.f, s2b = 0.f;
    float acc[2][6][4];
#pragma unroll
    for (int mt = 0; mt < 2; mt++)
#pragma unroll
        for (int nt = 0; nt < 6; nt++)
#pragma unroll
            for (int r = 0; r < 4; r++) acc[mt][nt][r] = 0.f;

    int w    = t >> 5, lane = t & 31;
    int wm   = w & 3,  wn   = w >> 2;
    int gid  = lane >> 2, tid = lane & 3;
    int wi   = t >> 1, whf = t & 1;

    uint32_t aAddr0 = (uint32_t)__cvta_generic_to_shared(
        &Xs[0][(wm * 32 + (lane & 15)) * XP + (lane >> 4) * 8]);
    uint32_t aAddr1 = aAddr0 + 16 * XP * 2;
    uint32_t bAddr  = (uint32_t)__cvta_generic_to_shared(
        &Ws[0][(wn * 48 + (lane & 7)) * WP + ((lane >> 3) & 1) * 8]);
    const uint32_t XBUF = 128 * XP * 2;
    const uint32_t WBUF = INNER * WP * 2;

    float2 xv[8];
    uint4 wv0, wv1;
#pragma unroll
    for (int j = 0; j < 8; j++)
        xv[j] = *(const float2*)(xb + (size_t)(ci * 8 + j) * HW);
    if (t < 192) {
        const uint4* src = (const uint4*)(g_Wt + wi * DIM + whf * 16);
        wv0 = src[0]; wv1 = src[1];
    }

    for (int kc = 0; kc < 24; kc++) {
        int buf = kc & 1;
#pragma unroll
        for (int j = 0; j < 8; j++) {
            s1a += xv[j].x; s2a += xv[j].x * xv[j].x;
            s1b += xv[j].y; s2b += xv[j].y * xv[j].y;
        }
        __nv_bfloat162 p0[4], p1[4];
#pragma unroll
        for (int j = 0; j < 4; j++) {
            p0[j] = __floats2bfloat162_rn(xv[2*j].x, xv[2*j+1].x);
            p1[j] = __floats2bfloat162_rn(xv[2*j].y, xv[2*j+1].y);
        }
        *(uint4*)&Xs[buf][(qi * 2)     * XP + ci * 8] = *(uint4*)p0;
        *(uint4*)&Xs[buf][(qi * 2 + 1) * XP + ci * 8] = *(uint4*)p1;
        if (t < 192) {
            uint4* dst = (uint4*)&Ws[buf][wi * WP + whf * 16];
            dst[0] = wv0; dst[1] = wv1;
        }
        __syncthreads();

        if (kc < 23) {
            int c0 = (kc + 1) * 32;
#pragma unroll
            for (int j = 0; j < 8; j++)
                xv[j] = *(const float2*)(xb + (size_t)(c0 + ci * 8 + j) * HW);
            if (t < 192) {
                const uint4* src = (const uint4*)(g_Wt + wi * DIM + c0 + whf * 16);
                wv0 = src[0]; wv1 = src[1];
            }
        }

        uint32_t xo = buf * XBUF, wo = buf * WBUF;
#pragma unroll
        for (int ks = 0; ks < 2; ks++) {
            uint32_t af0[4], af1[4];
            ldsm_x4(af0, aAddr0 + xo + ks * 32);
            ldsm_x4(af1, aAddr1 + xo + ks * 32);
            uint32_t bfrag[6][2];
#pragma unroll
            for (int nt = 0; nt < 6; nt++)
                ldsm_x2(bfrag[nt], bAddr + wo + nt * 8 * WP * 2 + ks * 32);
#pragma unroll
            for (int nt = 0; nt < 6; nt++) {
                mma_bf16(acc[0][nt], af0[0], af0[1], af0[2], af0[3],
                         bfrag[nt][0], bfrag[nt][1]);
                mma_bf16(acc[1][nt], af1[0], af1[1], af1[2], af1[3],
                         bfrag[nt][0], bfrag[nt][1]);
            }
        }
    }

    // token stats
    atomicAdd(&sumS[qi * 2],     s1a); atomicAdd(&sqS[qi * 2],     s2a);
    atomicAdd(&sumS[qi * 2 + 1], s1b); atomicAdd(&sqS[qi * 2 + 1], s2b);
    __syncthreads();
    if (t < 128) {
        float mu  = sumS[t] * (1.f / DIM);
        float var = sqS[t] * (1.f / DIM) - mu * mu;
        float r   = rsqrtf(var + EPS_LN);
        muS[t] = mu; rS[t] = r;
        g_mu[b * HW + q0 + t] = mu;
        g_r [b * HW + q0 + t] = r;
    }
    __syncthreads();

    // epilogue: y -> gelu -> logits
#pragma unroll
    for (int mt = 0; mt < 2; mt++) {
#pragma unroll
        for (int hf = 0; hf < 2; hf++) {
            int ql   = wm * 32 + mt * 16 + hf * 8 + gid;
            float mu = muS[ql], r = rS[ql];
            float pl[NTOK];
#pragma unroll
            for (int n = 0; n < NTOK; n++) pl[n] = 0.f;
#pragma unroll
            for (int nt = 0; nt < 6; nt++) {
#pragma unroll
                for (int ch = 0; ch < 2; ch++) {
                    int i   = wn * 48 + nt * 8 + tid * 2 + ch;
                    float v = acc[mt][nt][hf * 2 + ch];
                    float y = r * (v - mu * colsumS[i]) + bw1S[i];
                    float h = 0.5f * y * (1.f + erff(y * 0.70710678f));
#pragma unroll
                    for (int n = 0; n < NTOK; n++) pl[n] += h * w2S[i * NTOK + n];
                }
            }
#pragma unroll
            for (int n = 0; n < NTOK; n++) {
                pl[n] += __shfl_xor_sync(0xffffffffu, pl[n], 1);
                pl[n] += __shfl_xor_sync(0xffffffffu, pl[n], 2);
            }
            if (tid == 0) {
#pragma unroll
                for (int n = 0; n < NTOK; n++)
                    atomicAdd(&logitsS[ql * NTOK + n], pl[n]);
            }
        }
    }
    __syncthreads();
    for (int idx = t; idx < 128 * NTOK; idx += 256) {
        int n = idx >> 7, q = idx & 127;
        g_logitsT[((size_t)b * NTOK + n) * HW + q0 + q] = logitsS[q * NTOK + n];
    }
}

// ---------------- pass B: softmax over tokens, per (b, n) --------------------
__global__ void passB_kernel()
{
    int b = blockIdx.x;
    int w = threadIdx.x >> 5, lane = threadIdx.x & 31;
    const float* lp  = g_logitsT + ((size_t)b * NTOK + w) * HW;
    const float* mup = g_mu + (size_t)b * HW;
    const float* rp  = g_r  + (size_t)b * HW;

    float m = -1e30f;
    for (int j = 0; j < 32; j++) m = fmaxf(m, lp[lane + j * 32]);
#pragma unroll
    for (int o = 16; o; o >>= 1) m = fmaxf(m, __shfl_xor_sync(0xffffffffu, m, o));

    float Z = 0.f, Sm = 0.f;
    for (int j = 0; j < 32; j++) {
        int p  = lane + j * 32;
        float e = expf(lp[p] - m);
        Z  += e;
        Sm += mup[p] * rp[p] * e;
    }
#pragma unroll
    for (int o = 16; o; o >>= 1) {
        Z  += __shfl_xor_sync(0xffffffffu, Z,  o);
        Sm += __shfl_xor_sync(0xffffffffu, Sm, o);
    }
    float invZ = 1.f / Z;
    float* ap = g_attnwT + ((size_t)b * NTOK + w) * HW;
    for (int j = 0; j < 32; j++) {
        int p  = lane + j * 32;
        float e = expf(lp[p] - m);
        ap[p] = rp[p] * e * invZ;
    }
    if (lane == 0) g_S[b * NTOK + w] = Sm * invZ;
}

// ---------------- pass C: split-bf16 3-MMA GEMM  out[c,n] = x[c,:] @ aw[:,n] --
constexpr int AWP     = 1032;              // bf16 elems per aw row (1024 + 8 pad)
constexpr int AW_B    = NTOK * AWP * 2;    // 16512 bytes per (h|l) matrix
constexpr int XTP     = 40;                // per-warp x tile pitch (32 q + 8 pad)
constexpr int XTILE_B = 16 * XTP * 2;      // 1280 bytes per (h|l) per buffer
constexpr int WARPX_B = 4 * XTILE_B;       // 2 buffers x (h+l) = 5120 bytes
constexpr int SMEM_C  = 2 * AW_B + 8 * WARPX_B;  // 73984 bytes

__global__ __launch_bounds__(256) void passC_kernel(
    const float* __restrict__ x, const float* __restrict__ gamma,
    const float* __restrict__ beta, float* __restrict__ out)
{
    extern __shared__ __align__(16) char smem[];
    __nv_bfloat16* awh = (__nv_bfloat16*)smem;
    __nv_bfloat16* awl = (__nv_bfloat16*)(smem + AW_B);
    char* xtiles = smem + 2 * AW_B;

    int t = threadIdx.x, w = t >> 5, lane = t & 31;
    int blk  = blockIdx.x;
    int b    = blk / 6;
    int slab = blk % 6;

    // stage aw split into hi/lo bf16 (shared by all warps)
    const float4* awg = (const float4*)(g_attnwT + (size_t)b * NTOK * HW);
    for (int i = t; i < NTOK * HW / 4; i += 256) {
        float4 v = awg[i];
        int n = i >> 8;
        int q = (i & 255) << 2;
        __nv_bfloat16 h0 = __float2bfloat16(v.x), h1 = __float2bfloat16(v.y);
        __nv_bfloat16 h2 = __float2bfloat16(v.z), h3 = __float2bfloat16(v.w);
        __nv_bfloat16 l0 = __float2bfloat16(v.x - __bfloat162float(h0));
        __nv_bfloat16 l1 = __float2bfloat16(v.y - __bfloat162float(h1));
        __nv_bfloat16 l2 = __float2bfloat16(v.z - __bfloat162float(h2));
        __nv_bfloat16 l3 = __float2bfloat16(v.w - __bfloat162float(h3));
        __nv_bfloat16 hp[4] = {h0, h1, h2, h3};
        __nv_bfloat16 lp[4] = {l0, l1, l2, l3};
        *(uint2*)&awh[n * AWP + q] = *(uint2*)hp;
        *(uint2*)&awl[n * AWP + q] = *(uint2*)lp;
    }
    __syncthreads();

    // warp-private mainloop: 16 channels, K = 1024 in 32 chunks of 32 q
    int cw = slab * 128 + w * 16;
    const float* xg = x + ((size_t)b * DIM + cw) * HW;
    int lrow = lane >> 3;            // 0..3
    int lcol = (lane & 7) * 4;       // float col within chunk

    char* xw = xtiles + w * WARPX_B;
    uint32_t xw_s = (uint32_t)__cvta_generic_to_shared(xw);
    uint32_t aA   = xw_s + (lane & 15) * (XTP * 2) + (lane >> 4) * 16;
    uint32_t bAh  = (uint32_t)__cvta_generic_to_shared(awh)
                  + (lane & 7) * (AWP * 2) + ((lane >> 3) & 1) * 16;
    uint32_t bAl  = bAh + AW_B;

    float acc[4]  = {0.f, 0.f, 0.f, 0.f};
    float acc2[4] = {0.f, 0.f, 0.f, 0.f};

    float4 r[4];
#pragma unroll
    for (int j = 0; j < 4; j++)
        r[j] = *(const float4*)(xg + (size_t)(j * 4 + lrow) * HW + lcol);

    for (int ch = 0; ch < 32; ch++) {
        int buf = ch & 1;
        char* bb = xw + buf * (2 * XTILE_B);
#pragma unroll
        for (int j = 0; j < 4; j++) {
            int row = j * 4 + lrow;
            __nv_bfloat16 h0 = __float2bfloat16(r[j].x), h1 = __float2bfloat16(r[j].y);
            __nv_bfloat16 h2 = __float2bfloat16(r[j].z), h3 = __float2bfloat16(r[j].w);
            __nv_bfloat16 l0 = __float2bfloat16(r[j].x - __bfloat162float(h0));
            __nv_bfloat16 l1 = __float2bfloat16(r[j].y - __bfloat162float(h1));
            __nv_bfloat16 l2 = __float2bfloat16(r[j].z - __bfloat162float(h2));
            __nv_bfloat16 l3 = __float2bfloat16(r[j].w - __bfloat162float(h3));
            __nv_bfloat16 hp[4] = {h0, h1, h2, h3};
            __nv_bfloat16 lp[4] = {l0, l1, l2, l3};
            *(uint2*)(bb + row * (XTP * 2) + lcol * 2)            = *(uint2*)hp;
            *(uint2*)(bb + XTILE_B + row * (XTP * 2) + lcol * 2)  = *(uint2*)lp;
        }
        if (ch < 31) {
#pragma unroll
            for (int j = 0; j < 4; j++)
                r[j] = *(const float4*)(xg + (size_t)(j * 4 + lrow) * HW
                                        + (ch + 1) * 32 + lcol);
        }
        __syncwarp();
        uint32_t bo = buf * (2 * XTILE_B);
#pragma unroll
        for (int kt = 0; kt < 2; kt++) {
            uint32_t fh[4], fl[4], bh[2], bl[2];
            ldsm_x4(fh, aA + bo + kt * 32);
            ldsm_x4(fl, aA + bo + XTILE_B + kt * 32);
            ldsm_x2(bh, bAh + ch * 64 + kt * 32);
            ldsm_x2(bl, bAl + ch * 64 + kt * 32);
            mma_bf16(acc,  fh[0], fh[1], fh[2], fh[3], bh[0], bh[1]);
            mma_bf16(acc2, fh[0], fh[1], fh[2], fh[3], bl[0], bl[1]);
            mma_bf16(acc,  fl[0], fl[1], fl[2], fl[3], bh[0], bh[1]);
        }
    }

    // epilogue: out[b, c, n] = (gamma*(v - S_n) + beta) / 1024
    int n0 = (lane & 3) * 2;
    float S0 = g_S[b * NTOK + n0];
    float S1 = g_S[b * NTOK + n0 + 1];
    int m0 = lane >> 2;
#pragma unroll
    for (int half = 0; half < 2; half++) {
        int c = cw + m0 + half * 8;
        float g  = gamma[c], be = beta[c];
        float v0 = acc[half * 2 + 0] + acc2[half * 2 + 0];
        float v1 = acc[half * 2 + 1] + acc2[half * 2 + 1];
        float2 o;
        o.x = (g * (v0 - S0) + be) * (1.f / 1024.f);
        o.y = (g * (v1 - S1) + be) * (1.f / 1024.f);
        *(float2*)&out[(((size_t)b * DIM) + c) * NTOK + n0] = o;
    }
}

// ---------------- launcher ----------------------------------------------------
extern "C" void kernel_launch(void* const* d_in, const int* in_sizes, int n_in,
                              void* d_out, int out_size)
{
    const float* x     = (const float*)d_in[0];
    const float* gamma = (const float*)d_in[1];
    const float* beta  = (const float*)d_in[2];
    const float* w1    = (const float*)d_in[3];
    const float* b1    = (const float*)d_in[4];
    const float* w2    = (const float*)d_in[5];
    // d_in[6] = b2: constant shift before token softmax -> cancels exactly.
    float* out = (float*)d_out;

    static bool attr_set = false;
    if (!attr_set) {
        cudaFuncSetAttribute(passC_kernel,
                             cudaFuncAttributeMaxDynamicSharedMemorySize, SMEM_C);
        attr_set = true;
    }

    setup_kernel<<<INNER, 256>>>(w1, gamma, beta, b1);
    passA_kernel<<<NB * 8, 256>>>(x, w2);
    passB_kernel<<<NB, 256>>>();
    passC_kernel<<<NB * 6, 256, SMEM_C>>>(x, gamma, beta, out);
}

// round 8
// speedup vs baseline: 1.2737x; 1.0303x over previous
#include <cuda_runtime.h>
#include <cuda_bf16.h>
#include <cstdint>

#define DIM   768
#define INNER 96
#define NTOK  8
#define HW    1024
#define NB    64
#define EPS_LN 1e-5f

typedef unsigned long long ull;

// ---------------- scratch (device globals; no allocation allowed) ------------
__device__ __nv_bfloat16 g_Wt[INNER * DIM];        // W1*gamma, bf16, [i][c]
__device__ float g_colsum[INNER];
__device__ float g_bw1[INNER];
__device__ float g_r[NB * HW];
__device__ float g_mu[NB * HW];
__device__ float g_logitsT[NB * NTOK * HW];
__device__ float g_attnwT[NB * NTOK * HW];         // r_p * attn[p,n], [b][n][p]
__device__ float g_S[NB * NTOK];

// ---------------- helpers ----------------------------------------------------
__device__ __forceinline__ void mma_bf16(float* d,
    uint32_t a0, uint32_t a1, uint32_t a2, uint32_t a3,
    uint32_t b0, uint32_t b1)
{
    asm volatile(
        "mma.sync.aligned.m16n8k16.row.col.f32.bf16.bf16.f32 "
        "{%0,%1,%2,%3}, {%4,%5,%6,%7}, {%8,%9}, {%0,%1,%2,%3};"
        : "+f"(d[0]), "+f"(d[1]), "+f"(d[2]), "+f"(d[3])
        : "r"(a0), "r"(a1), "r"(a2), "r"(a3), "r"(b0), "r"(b1));
}

__device__ __forceinline__ void ldsm_x4(uint32_t* r, uint32_t addr) {
    asm volatile("ldmatrix.sync.aligned.m8n8.x4.shared.b16 {%0,%1,%2,%3}, [%4];"
        : "=r"(r[0]), "=r"(r[1]), "=r"(r[2]), "=r"(r[3]) : "r"(addr));
}
__device__ __forceinline__ void ldsm_x2(uint32_t* r, uint32_t addr) {
    asm volatile("ldmatrix.sync.aligned.m8n8.x2.shared.b16 {%0,%1}, [%2];"
        : "=r"(r[0]), "=r"(r[1]) : "r"(addr));
}

// split fp32 pair -> hi bf16x2 + residual bf16x2 (bf16->f32 is a 16-bit shift)
__device__ __forceinline__ void split2(float2 v, uint32_t& h, uint32_t& l) {
    __nv_bfloat162 hb = __floats2bfloat162_rn(v.x, v.y);
    uint32_t hu = *(uint32_t*)&hb;
    float f0 = __uint_as_float(hu << 16);
    float f1 = __uint_as_float(hu & 0xffff0000u);
    __nv_bfloat162 lb = __floats2bfloat162_rn(v.x - f0, v.y - f1);
    h = hu; l = *(uint32_t*)&lb;
}

// ---------------- setup: fold gamma into W1, precompute column sums ----------
__global__ void setup_kernel(const float* __restrict__ w1,
                             const float* __restrict__ gamma,
                             const float* __restrict__ beta,
                             const float* __restrict__ b1)
{
    int i = blockIdx.x;
    int t = threadIdx.x;
    float a = 0.f, bs = 0.f;
    for (int c = t; c < DIM; c += 256) {
        float w  = w1[c * INNER + i];
        float gw = gamma[c] * w;
        g_Wt[i * DIM + c] = __float2bfloat16(gw);
        a  += gw;
        bs += beta[c] * w;
    }
    __shared__ float ra[256], rb[256];
    ra[t] = a; rb[t] = bs;
    __syncthreads();
    for (int s = 128; s > 0; s >>= 1) {
        if (t < s) { ra[t] += ra[t + s]; rb[t] += rb[t + s]; }
        __syncthreads();
    }
    if (t == 0) { g_colsum[i] = ra[0]; g_bw1[i] = rb[0] + b1[i]; }
}

// ---------------- pass A: LN stats + MLP logits, pipelined bf16 mma ----------
constexpr int XP = 40;
constexpr int WP = 40;

__global__ __launch_bounds__(256, 2) void passA_kernel(
    const float* __restrict__ x, const float* __restrict__ w2)
{
    __shared__ __nv_bfloat16 Xs[2][128 * XP];
    __shared__ __nv_bfloat16 Ws[2][INNER * WP];
    __shared__ float logitsS[128 * NTOK];
    __shared__ float sumS[128], sqS[128], muS[128], rS[128];
    __shared__ float w2S[INNER * NTOK];
    __shared__ float colsumS[INNER], bw1S[INNER];

    int t   = threadIdx.x;
    int blk = blockIdx.x;
    int b   = blk >> 3;
    int q0  = (blk & 7) << 7;

    for (int i = t; i < 128 * NTOK; i += 256) logitsS[i] = 0.f;
    if (t < 128) { sumS[t] = 0.f; sqS[t] = 0.f; }
    for (int i = t; i < INNER * NTOK; i += 256) w2S[i] = w2[i];
    if (t < INNER) { colsumS[t] = g_colsum[t]; bw1S[t] = g_bw1[t]; }

    int qi = t & 63;
    int ci = t >> 6;
    const float* xb = x + ((size_t)b * DIM) * HW + q0 + qi * 2;

    float s1a = 0.f, s1b = 0.f, s2a = 0.f, s2b = 0.f;
    float acc[2][6][4];
#pragma unroll
    for (int mt = 0; mt < 2; mt++)
#pragma unroll
        for (int nt = 0; nt < 6; nt++)
#pragma unroll
            for (int r = 0; r < 4; r++) acc[mt][nt][r] = 0.f;

    int w    = t >> 5, lane = t & 31;
    int wm   = w & 3,  wn   = w >> 2;
    int gid  = lane >> 2, tid = lane & 3;
    int wi   = t >> 1, whf = t & 1;

    uint32_t aAddr0 = (uint32_t)__cvta_generic_to_shared(
        &Xs[0][(wm * 32 + (lane & 15)) * XP + (lane >> 4) * 8]);
    uint32_t aAddr1 = aAddr0 + 16 * XP * 2;
    uint32_t bAddr  = (uint32_t)__cvta_generic_to_shared(
        &Ws[0][(wn * 48 + (lane & 7)) * WP + ((lane >> 3) & 1) * 8]);
    const uint32_t XBUF = 128 * XP * 2;
    const uint32_t WBUF = INNER * WP * 2;

    float2 xv[8];
    uint4 wv0, wv1;
#pragma unroll
    for (int j = 0; j < 8; j++)
        xv[j] = *(const float2*)(xb + (size_t)(ci * 8 + j) * HW);
    if (t < 192) {
        const uint4* src = (const uint4*)(g_Wt + wi * DIM + whf * 16);
        wv0 = src[0]; wv1 = src[1];
    }

    for (int kc = 0; kc < 24; kc++) {
        int buf = kc & 1;
#pragma unroll
        for (int j = 0; j < 8; j++) {
            s1a += xv[j].x; s2a += xv[j].x * xv[j].x;
            s1b += xv[j].y; s2b += xv[j].y * xv[j].y;
        }
        __nv_bfloat162 p0[4], p1[4];
#pragma unroll
        for (int j = 0; j < 4; j++) {
            p0[j] = __floats2bfloat162_rn(xv[2*j].x, xv[2*j+1].x);
            p1[j] = __floats2bfloat162_rn(xv[2*j].y, xv[2*j+1].y);
        }
        *(uint4*)&Xs[buf][(qi * 2)     * XP + ci * 8] = *(uint4*)p0;
        *(uint4*)&Xs[buf][(qi * 2 + 1) * XP + ci * 8] = *(uint4*)p1;
        if (t < 192) {
            uint4* dst = (uint4*)&Ws[buf][wi * WP + whf * 16];
            dst[0] = wv0; dst[1] = wv1;
        }
        __syncthreads();

        if (kc < 23) {
            int c0 = (kc + 1) * 32;
#pragma unroll
            for (int j = 0; j < 8; j++)
                xv[j] = *(const float2*)(xb + (size_t)(c0 + ci * 8 + j) * HW);
            if (t < 192) {
                const uint4* src = (const uint4*)(g_Wt + wi * DIM + c0 + whf * 16);
                wv0 = src[0]; wv1 = src[1];
            }
        }

        uint32_t xo = buf * XBUF, wo = buf * WBUF;
#pragma unroll
        for (int ks = 0; ks < 2; ks++) {
            uint32_t af0[4], af1[4];
            ldsm_x4(af0, aAddr0 + xo + ks * 32);
            ldsm_x4(af1, aAddr1 + xo + ks * 32);
            uint32_t bfrag[6][2];
#pragma unroll
            for (int nt = 0; nt < 6; nt++)
                ldsm_x2(bfrag[nt], bAddr + wo + nt * 8 * WP * 2 + ks * 32);
#pragma unroll
            for (int nt = 0; nt < 6; nt++) {
                mma_bf16(acc[0][nt], af0[0], af0[1], af0[2], af0[3],
                         bfrag[nt][0], bfrag[nt][1]);
                mma_bf16(acc[1][nt], af1[0], af1[1], af1[2], af1[3],
                         bfrag[nt][0], bfrag[nt][1]);
            }
        }
    }

    // token stats
    atomicAdd(&sumS[qi * 2],     s1a); atomicAdd(&sqS[qi * 2],     s2a);
    atomicAdd(&sumS[qi * 2 + 1], s1b); atomicAdd(&sqS[qi * 2 + 1], s2b);
    __syncthreads();
    if (t < 128) {
        float mu  = sumS[t] * (1.f / DIM);
        float var = sqS[t] * (1.f / DIM) - mu * mu;
        float r   = rsqrtf(var + EPS_LN);
        muS[t] = mu; rS[t] = r;
        g_mu[b * HW + q0 + t] = mu;
        g_r [b * HW + q0 + t] = r;
    }
    __syncthreads();

    // epilogue: y -> gelu -> logits
#pragma unroll
    for (int mt = 0; mt < 2; mt++) {
#pragma unroll
        for (int hf = 0; hf < 2; hf++) {
            int ql   = wm * 32 + mt * 16 + hf * 8 + gid;
            float mu = muS[ql], r = rS[ql];
            float pl[NTOK];
#pragma unroll
            for (int n = 0; n < NTOK; n++) pl[n] = 0.f;
#pragma unroll
            for (int nt = 0; nt < 6; nt++) {
#pragma unroll
                for (int ch = 0; ch < 2; ch++) {
                    int i   = wn * 48 + nt * 8 + tid * 2 + ch;
                    float v = acc[mt][nt][hf * 2 + ch];
                    float y = r * (v - mu * colsumS[i]) + bw1S[i];
                    float h = 0.5f * y * (1.f + erff(y * 0.70710678f));
#pragma unroll
                    for (int n = 0; n < NTOK; n++) pl[n] += h * w2S[i * NTOK + n];
                }
            }
#pragma unroll
            for (int n = 0; n < NTOK; n++) {
                pl[n] += __shfl_xor_sync(0xffffffffu, pl[n], 1);
                pl[n] += __shfl_xor_sync(0xffffffffu, pl[n], 2);
            }
            if (tid == 0) {
#pragma unroll
                for (int n = 0; n < NTOK; n++)
                    atomicAdd(&logitsS[ql * NTOK + n], pl[n]);
            }
        }
    }
    __syncthreads();
    for (int idx = t; idx < 128 * NTOK; idx += 256) {
        int n = idx >> 7, q = idx & 127;
        g_logitsT[((size_t)b * NTOK + n) * HW + q0 + q] = logitsS[q * NTOK + n];
    }
}

// ---------------- pass B: softmax over tokens, per (b, n) --------------------
__global__ void passB_kernel()
{
    int b = blockIdx.x;
    int w = threadIdx.x >> 5, lane = threadIdx.x & 31;
    const float* lp  = g_logitsT + ((size_t)b * NTOK + w) * HW;
    const float* mup = g_mu + (size_t)b * HW;
    const float* rp  = g_r  + (size_t)b * HW;

    float m = -1e30f;
    for (int j = 0; j < 32; j++) m = fmaxf(m, lp[lane + j * 32]);
#pragma unroll
    for (int o = 16; o; o >>= 1) m = fmaxf(m, __shfl_xor_sync(0xffffffffu, m, o));

    float Z = 0.f, Sm = 0.f;
    for (int j = 0; j < 32; j++) {
        int p  = lane + j * 32;
        float e = expf(lp[p] - m);
        Z  += e;
        Sm += mup[p] * rp[p] * e;
    }
#pragma unroll
    for (int o = 16; o; o >>= 1) {
        Z  += __shfl_xor_sync(0xffffffffu, Z,  o);
        Sm += __shfl_xor_sync(0xffffffffu, Sm, o);
    }
    float invZ = 1.f / Z;
    float* ap = g_attnwT + ((size_t)b * NTOK + w) * HW;
    for (int j = 0; j < 32; j++) {
        int p  = lane + j * 32;
        float e = expf(lp[p] - m);
        ap[p] = rp[p] * e * invZ;
    }
    if (lane == 0) g_S[b * NTOK + w] = Sm * invZ;
}

// ---------------- pass C v3: register-direct split-bf16 MMA, zero smem -------
// out[c,n] = sum_q x[c,q]*aw[q,n]. A and B fragments built straight from
// coalesced gmem loads per the PTX m16n8k16 lane layout. No STS/ldmatrix/sync.
struct KData { float2 a0, a1, a2, a3, b0, b1; };

__device__ __forceinline__ void ld_k(KData& d, const float* xr, const float* xr8,
                                     const float* br, int k0)
{
    d.a0 = *(const float2*)(xr  + k0);
    d.a1 = *(const float2*)(xr8 + k0);
    d.a2 = *(const float2*)(xr  + k0 + 8);
    d.a3 = *(const float2*)(xr8 + k0 + 8);
    d.b0 = *(const float2*)(br  + k0);
    d.b1 = *(const float2*)(br  + k0 + 8);
}

__global__ __launch_bounds__(256) void passC_kernel(
    const float* __restrict__ x, const float* __restrict__ gamma,
    const float* __restrict__ beta, float* __restrict__ out)
{
    int t = threadIdx.x, w = t >> 5, lane = t & 31;
    int blk  = blockIdx.x;
    int b    = blk / 6;
    int slab = blk % 6;

    int g  = lane >> 2;          // row-group (A rows / B col n)
    int tq = (lane & 3) * 2;     // k-pair offset

    int cw = slab * 128 + w * 16;
    const float* xr  = x + ((size_t)b * DIM + cw + g) * HW + tq;
    const float* xr8 = xr + 8 * HW;
    const float* br  = g_attnwT + ((size_t)b * NTOK + g) * HW + tq;

    float acc[4]  = {0.f, 0.f, 0.f, 0.f};
    float acc2[4] = {0.f, 0.f, 0.f, 0.f};

    KData buf[2];
    ld_k(buf[0], xr, xr8, br, 0);
    ld_k(buf[1], xr, xr8, br, 16);

#pragma unroll 2
    for (int ks = 0; ks < 64; ks++) {
        KData cur = buf[ks & 1];
        if (ks < 62) ld_k(buf[ks & 1], xr, xr8, br, (ks + 2) * 16);

        uint32_t ah0, ah1, ah2, ah3, al0, al1, al2, al3;
        uint32_t bh0, bh1, bl0, bl1;
        split2(cur.a0, ah0, al0);
        split2(cur.a1, ah1, al1);
        split2(cur.a2, ah2, al2);
        split2(cur.a3, ah3, al3);
        split2(cur.b0, bh0, bl0);
        split2(cur.b1, bh1, bl1);

        mma_bf16(acc,  ah0, ah1, ah2, ah3, bh0, bh1);
        mma_bf16(acc2, ah0, ah1, ah2, ah3, bl0, bl1);
        mma_bf16(acc,  al0, al1, al2, al3, bh0, bh1);
    }

    // epilogue: c0,c1 = rows g cols 2t,2t+1 ; c2,c3 = rows g+8
    int n0 = (lane & 3) * 2;
    float S0 = g_S[b * NTOK + n0];
    float S1 = g_S[b * NTOK + n0 + 1];
    int m0 = lane >> 2;
#pragma unroll
    for (int half = 0; half < 2; half++) {
        int c = cw + m0 + half * 8;
        float gm = gamma[c], be = beta[c];
        float v0 = acc[half * 2 + 0] + acc2[half * 2 + 0];
        float v1 = acc[half * 2 + 1] + acc2[half * 2 + 1];
        float2 o;
        o.x = (gm * (v0 - S0) + be) * (1.f / 1024.f);
        o.y = (gm * (v1 - S1) + be) * (1.f / 1024.f);
        *(float2*)&out[(((size_t)b * DIM) + c) * NTOK + n0] = o;
    }
}

// ---------------- launcher ----------------------------------------------------
extern "C" void kernel_launch(void* const* d_in, const int* in_sizes, int n_in,
                              void* d_out, int out_size)
{
    const float* x     = (const float*)d_in[0];
    const float* gamma = (const float*)d_in[1];
    const float* beta  = (const float*)d_in[2];
    const float* w1    = (const float*)d_in[3];
    const float* b1    = (const float*)d_in[4];
    const float* w2    = (const float*)d_in[5];
    // d_in[6] = b2: constant shift before token softmax -> cancels exactly.
    float* out = (float*)d_out;

    setup_kernel<<<INNER, 256>>>(w1, gamma, beta, b1);
    passA_kernel<<<NB * 8, 256>>>(x, w2);
    passB_kernel<<<NB, 256>>>();
    passC_kernel<<<NB * 6, 256>>>(x, gamma, beta, out);
}